// round 14
// baseline (speedup 1.0000x reference)
#include <cuda_runtime.h>
#include <math.h>

typedef unsigned long long ull;

#define T_STEPS 2048
#define BATCH   32
#define DIM     512
#define NA      33554432u     // 2048*32*512

#define NREC      64
#define GEMM_CTAS 6144        // 512 row-chunks * 4 n-tiles * 3 gates
#define CHUNKS    512
#define TILES_PER_CHUNK 12

// ---------------------------------------------------------------------------
// Static device scratch (no allocations anywhere)
// ---------------------------------------------------------------------------
__device__ float g_Ai[NA];                 // x@Wi^T + 2bi          [t*32+b][j]
__device__ float g_Az[NA];                 // x@Wz^T + bz + bi
__device__ float g_Ao[NA];                 // x@Wo^T + bo + bi
// Hidden state double buffer, thread-major scrambled layout:
//   ull element (u, tid) at [u*256 + tid] holds the k-pair
//   h[b][2*k2], h[b][2*k2+1]  where  tid = (k2>>4)*16 + (b>>1),
//   u = (b&1)*16 + (k2&15).   Buffer 0 must be zero at kernel start.
__device__ ull g_hx[2][32 * 256];
__device__ unsigned int g_flag[NREC];      // per-CTA step flags (monotonic)
__device__ unsigned int g_bar2;            // completion counter (state reset)
__device__ unsigned int g_done[CHUNKS];    // per-chunk gemm completion (-> 12)

// ---------------------------------------------------------------------------
// f32x2 + relaxed-sync helpers
// ---------------------------------------------------------------------------
__device__ __forceinline__ ull pack2(float x, float y) {
    ull r; asm("mov.b64 %0,{%1,%2};" : "=l"(r) : "f"(x), "f"(y)); return r;
}
__device__ __forceinline__ void unpack2(ull v, float& x, float& y) {
    asm("mov.b64 {%0,%1},%2;" : "=f"(x), "=f"(y) : "l"(v));
}
__device__ __forceinline__ void fma2(ull& c, ull a, ull b) {
    asm("fma.rn.f32x2 %0,%1,%2,%0;" : "+l"(c) : "l"(a), "l"(b));
}
__device__ __forceinline__ void red_add(unsigned int* p, unsigned int v) {
    asm volatile("red.relaxed.gpu.global.add.u32 [%0], %1;" :: "l"(p), "r"(v) : "memory");
}
__device__ __forceinline__ unsigned int ld_rlx(const unsigned int* p) {
    unsigned int v;
    asm volatile("ld.relaxed.gpu.global.u32 %0, [%1];" : "=r"(v) : "l"(p) : "memory");
    return v;
}
__device__ __forceinline__ void st_rlx(unsigned int* p, unsigned int v) {
    asm volatile("st.relaxed.gpu.global.u32 [%0], %1;" :: "l"(p), "r"(v) : "memory");
}

// ---------------------------------------------------------------------------
// SMEM: rec steady-state: sW 8*256 ull (16KB) + red 2048 f (8KB)
//       rec epilogue:     sH 32*257 ull (65792 B)   <- sizing term
//       gemm:             sX/sW 2*128*9 ull (18KB)
// ---------------------------------------------------------------------------
#define MEGA_SMEM (32 * 257 * 8)
#define KP 9

// ---------------------------------------------------------------------------
// GEMM role: one 128x128 tile of one gate. Publishes g_done[chunk].
// ---------------------------------------------------------------------------
__device__ void gemm_role(
    ull* sm, int local,
    const float* __restrict__ X,
    const float* __restrict__ Wi, const float* __restrict__ Wz,
    const float* __restrict__ Wo,
    const float* __restrict__ bi, const float* __restrict__ bz,
    const float* __restrict__ bo)
{
    const int chunk = local / TILES_PER_CHUNK;
    const int sub   = local % TILES_PER_CHUNK;
    const int z     = sub >> 2;
    const int yt    = sub & 3;

    const float* W  = (z == 0) ? Wi : (z == 1) ? Wz : Wo;
    const float* b1 = (z == 0) ? bi : (z == 1) ? bz : bo;
    float* C = (z == 0) ? g_Ai : (z == 1) ? g_Az : g_Ao;

    ull* sX = sm;
    ull* sW = sm + 128 * KP;

    const int tid  = threadIdx.x;
    const int r    = tid >> 1;
    const int half = tid & 1;
    const size_t xrow = (size_t)(chunk * 128 + r) * 512 + half * 8;
    const size_t wrow = (size_t)(yt * 128 + r) * 512 + half * 8;

    const int m0 = (tid >> 4) * 8;
    const int n0 = (tid & 15) * 8;

    ull acc[8][8];
    #pragma unroll
    for (int i = 0; i < 8; ++i)
        #pragma unroll
        for (int j = 0; j < 8; ++j) acc[i][j] = 0ull;

    float4 px0 = __ldg((const float4*)(X + xrow));
    float4 px1 = __ldg((const float4*)(X + xrow) + 1);
    float4 pw0 = __ldg((const float4*)(W + wrow));
    float4 pw1 = __ldg((const float4*)(W + wrow) + 1);

    for (int kt = 0; kt < 32; ++kt) {
        __syncthreads();
        ull* dx = &sX[r * KP + half * 4];
        dx[0] = pack2(px0.x, px0.y);  dx[1] = pack2(px0.z, px0.w);
        dx[2] = pack2(px1.x, px1.y);  dx[3] = pack2(px1.z, px1.w);
        ull* dw = &sW[r * KP + half * 4];
        dw[0] = pack2(pw0.x, pw0.y);  dw[1] = pack2(pw0.z, pw0.w);
        dw[2] = pack2(pw1.x, pw1.y);  dw[3] = pack2(pw1.z, pw1.w);
        __syncthreads();

        if (kt + 1 < 32) {
            const float4* xp = (const float4*)(X + xrow + (size_t)(kt + 1) * 16);
            const float4* wp = (const float4*)(W + wrow + (size_t)(kt + 1) * 16);
            px0 = __ldg(xp);  px1 = __ldg(xp + 1);
            pw0 = __ldg(wp);  pw1 = __ldg(wp + 1);
        }

        #pragma unroll
        for (int k2 = 0; k2 < 8; ++k2) {
            ull a[8], bb[8];
            #pragma unroll
            for (int i = 0; i < 8; ++i) a[i]  = sX[(m0 + i) * KP + k2];
            #pragma unroll
            for (int j = 0; j < 8; ++j) bb[j] = sW[(n0 + j) * KP + k2];
            #pragma unroll
            for (int i = 0; i < 8; ++i)
                #pragma unroll
                for (int j = 0; j < 8; ++j) fma2(acc[i][j], a[i], bb[j]);
        }
    }

    float bias[8];
    #pragma unroll
    for (int j = 0; j < 8; ++j) {
        int n = yt * 128 + n0 + j;
        bias[j] = __ldg(b1 + n) + __ldg(bi + n);
    }
    #pragma unroll
    for (int i = 0; i < 8; ++i) {
        size_t row = (size_t)(chunk * 128 + m0 + i);
        float v[8];
        #pragma unroll
        for (int j = 0; j < 8; ++j) {
            float lo, hi; unpack2(acc[i][j], lo, hi);
            v[j] = lo + hi + bias[j];
        }
        float4* dst = (float4*)(C + row * 512 + yt * 128 + n0);
        dst[0] = make_float4(v[0], v[1], v[2], v[3]);
        dst[1] = make_float4(v[4], v[5], v[6], v[7]);
    }

    __threadfence();
    __syncthreads();
    if (tid == 0) red_add(&g_done[chunk], 1u);
}

// ---------------------------------------------------------------------------
// Recurrence role (blocks 0..63)
// ---------------------------------------------------------------------------
__device__ void rec_role(
    ull* sm,
    const float* __restrict__ Wi,
    const float* __restrict__ Wy,
    const float* __restrict__ by,
    float* __restrict__ out)
{
    ull*   sW  = sm;                       // Wi slice [j][k2], 8 x 256 ull
    float* red = (float*)(sm + 2048);      // partials [warp][b*8+j], 2048 f
    ull*   redu = (ull*)red;

    const int tid  = threadIdx.x;
    const int bid  = blockIdx.x;
    const int j0   = bid * 8;
    const int lane = tid & 31;
    const int w    = tid >> 5;
    const int k2g  = tid >> 4;            // k2 group: k2 in [k2g*16, +16)
    const int k2base = k2g * 16;
    const int gb   = tid >> 3;            // gate-phase batch row
    const int gj   = tid & 7;             // gate-phase column (local j)

    // h_new scatter address components (constant per thread)
    const int k2w = bid * 4 + (gj >> 1);
    const int u_w = (gb & 1) * 16 + (k2w & 15);
    const int rt_w = (k2w >> 4) * 16 + (gb >> 1);
    const int hoff = (u_w * 256 + rt_w) * 2 + (gj & 1);

    // Stage this CTA's 8 Wi rows once (2048 ull)
    const ull* Wi8 = (const ull*)Wi;
    #pragma unroll
    for (int c = 0; c < 8; ++c) {
        int li = c * 256 + tid;
        sW[li] = __ldg(Wi8 + (size_t)(j0 + (li >> 8)) * 256 + (li & 255));
    }
    __syncthreads();

    for (int t = 0; t < T_STEPS; ++t) {
        // Wait for this timestep's pre-activations (every 4 steps)
        if ((t & 3) == 0) {
            if (tid == 0) {
                const unsigned int* f = &g_done[t >> 2];
                while (ld_rlx(f) < TILES_PER_CHUNK) { }
            }
            __syncthreads();
        }

        // Gate pre-activations (independent of h; hide behind the dot)
        size_t ar = ((size_t)(t * 32 + gb)) * 512 + j0 + gj;
        float ai = __ldcg(&g_Ai[ar]);
        float az = __ldcg(&g_Az[ar]);
        float ao = __ldcg(&g_Ao[ar]);

        // h: 32 coalesced LDG.64 straight into registers (no SMEM staging)
        const ull* hb = g_hx[t & 1];
        ull hu[32];
        #pragma unroll
        for (int u = 0; u < 32; ++u) hu[u] = __ldcg(hb + u * 256 + tid);

        // dot: thread covers (b0,b1) x 8 j over its 16 k-pairs; w via LDS.128
        ull acc[2][8];
        #pragma unroll
        for (int jj = 0; jj < 8; ++jj) { acc[0][jj] = 0ull; acc[1][jj] = 0ull; }
        #pragma unroll
        for (int q2 = 0; q2 < 8; ++q2) {
            #pragma unroll
            for (int jj = 0; jj < 8; ++jj) {
                ulonglong2 wv = *(const ulonglong2*)(sW + jj * 256 + k2base + 2 * q2);
                fma2(acc[0][jj], hu[2 * q2],      wv.x);
                fma2(acc[0][jj], hu[2 * q2 + 1],  wv.y);
                fma2(acc[1][jj], hu[16 + 2 * q2], wv.x);
                fma2(acc[1][jj], hu[17 + 2 * q2], wv.y);
            }
        }

        // collapse k-pair halves + merge the warp's two k2-groups (bfly 16)
        float val[2][8];
        #pragma unroll
        for (int rr = 0; rr < 2; ++rr)
            #pragma unroll
            for (int jj = 0; jj < 8; ++jj) {
                float lo, hi; unpack2(acc[rr][jj], lo, hi);
                float v = lo + hi;
                v += __shfl_xor_sync(0xffffffffu, v, 16);
                val[rr][jj] = v;
            }

        // lanes 0-15 publish warp partials: red[w][b][j]
        if (lane < 16) {
            #pragma unroll
            for (int rr = 0; rr < 2; ++rr)
                #pragma unroll
                for (int m = 0; m < 4; ++m)
                    redu[w * 128 + (2 * lane + rr) * 4 + m] =
                        pack2(val[rr][2 * m], val[rr][2 * m + 1]);
        }
        __syncthreads();

        // cross-warp reduce -> hWi[b][j]
        float s = 0.0f;
        #pragma unroll
        for (int ww = 0; ww < 8; ++ww) s += red[ww * 256 + tid];

        // gates (biases pre-folded into A arrays)
        float zi = 1.0f / (1.0f + __expf(-(ai + s)));
        float zz = 1.0f / (1.0f + __expf(-(az + s)));
        float zo = 1.0f / (1.0f + __expf(-(ao + s)));
        float hn = zo * tanhf(zi * zz);
        ((float*)g_hx[(t + 1) & 1])[hoff] = hn;

        // flag barrier: 64 flags polled in parallel
        __threadfence();
        __syncthreads();
        if (tid == 0) st_rlx(&g_flag[bid], (unsigned int)(t + 1));
        if (tid < NREC) {
            const unsigned int tgt = (unsigned int)(t + 1);
            while (ld_rlx(&g_flag[tid]) < tgt) { }
        }
        __syncthreads();
    }

    // ---- Epilogue: final h is in buffer 0 ----
    {
        const ull* hb = g_hx[0];
        ull hu[32];
        #pragma unroll
        for (int u = 0; u < 32; ++u) hu[u] = __ldcg(hb + u * 256 + tid);

        // scatter to sH[b][k2] (whole SMEM reused; sW/red dead now)
        __syncthreads();
        ull* sH = sm;
        const int bp = tid & 15;
        #pragma unroll
        for (int u = 0; u < 32; ++u) {
            int b  = 2 * bp + (u >> 4);
            int k2 = k2base + (u & 15);
            sH[b * 257 + k2] = hu[u];
        }
        __syncthreads();

        // barrier 2049: everyone has read buffer 0 (reads proven complete
        // by the sH data dependency) before anyone zeroes it
        if (tid == 0) st_rlx(&g_flag[bid], 2049u);
        if (tid < NREC) { while (ld_rlx(&g_flag[tid]) < 2049u) { } }
        __syncthreads();

        // zero my slice of buffer 0 for the next graph replay
        if (tid < 128) g_hx[0][bid * 128 + tid] = 0ull;

        // out[b][j0+gj] = h[b][:] . Wy[j0+gj][:] + by
        const ull* wy2 = (const ull*)(Wy + (size_t)(j0 + gj) * 512);
        ull o = 0ull;
        #pragma unroll 8
        for (int k2 = 0; k2 < 256; ++k2)
            fma2(o, sH[gb * 257 + k2], __ldg(wy2 + k2));
        float lo, hi; unpack2(o, lo, hi);
        out[gb * 512 + j0 + gj] = lo + hi + __ldg(by + j0 + gj);
    }

    // ---- completion + state reset for the next replay ----
    __threadfence();
    __syncthreads();
    if (tid == 0) red_add(&g_bar2, 1u);
    if (bid == 0) {
        if (tid == 0) { while (ld_rlx(&g_bar2) < NREC) { } }
        __syncthreads();
        if (tid < NREC) st_rlx(&g_flag[tid], 0u);
        for (int i = tid; i < CHUNKS; i += 256) st_rlx(&g_done[i], 0u);
        __threadfence();
        __syncthreads();
        if (tid == 0) st_rlx(&g_bar2, 0u);
    }
}

// ---------------------------------------------------------------------------
// Fused persistent kernel (1 CTA/SM by registers -> rec SMs are exclusive)
// ---------------------------------------------------------------------------
__global__ __launch_bounds__(256, 1) void mega_kernel(
    const float* __restrict__ word,
    const float* __restrict__ Wi, const float* __restrict__ bi,
    const float* __restrict__ Wz, const float* __restrict__ bz,
    const float* __restrict__ Wo, const float* __restrict__ bo,
    const float* __restrict__ Wy, const float* __restrict__ by,
    float* __restrict__ out)
{
    extern __shared__ ull sm[];
    if (blockIdx.x < NREC) {
        rec_role(sm, Wi, Wy, by, out);
    } else {
        gemm_role(sm, blockIdx.x - NREC, word, Wi, Wz, Wo, bi, bz, bo);
    }
}

// ---------------------------------------------------------------------------
// Launch (single graph node)
// ---------------------------------------------------------------------------
extern "C" void kernel_launch(void* const* d_in, const int* in_sizes, int n_in,
                              void* d_out, int out_size)
{
    const float* word = (const float*)d_in[0];
    // d_in[1]=Wf, d_in[2]=bf are dead in the reference
    const float* Wi = (const float*)d_in[3];
    const float* bi = (const float*)d_in[4];
    const float* Wz = (const float*)d_in[5];
    const float* bz = (const float*)d_in[6];
    const float* Wo = (const float*)d_in[7];
    const float* bo = (const float*)d_in[8];
    const float* Wy = (const float*)d_in[9];
    const float* by = (const float*)d_in[10];
    float* out = (float*)d_out;

    cudaFuncSetAttribute(mega_kernel,
                         cudaFuncAttributeMaxDynamicSharedMemorySize, MEGA_SMEM);

    mega_kernel<<<NREC + GEMM_CTAS, 256, MEGA_SMEM>>>(
        word, Wi, bi, Wz, bz, Wo, bo, Wy, by, out);
}

// round 15
// speedup vs baseline: 2.9370x; 2.9370x over previous
#include <cuda_runtime.h>
#include <math.h>

typedef unsigned long long ull;

#define T_STEPS 2048
#define BATCH   32
#define DIM     512
#define NA      33554432u     // 2048*32*512

#define NREC      64
#define GEMM_CTAS 6144        // 512 row-chunks * 4 n-tiles * 3 gates
#define CHUNKS    512
#define TILES_PER_CHUNK 12

// ---------------------------------------------------------------------------
// Static device scratch (no allocations anywhere)
// ---------------------------------------------------------------------------
__device__ float g_Ai[NA];                 // x@Wi^T + 2bi          [t*32+b][j]
__device__ float g_Az[NA];                 // x@Wz^T + bz + bi
__device__ float g_Ao[NA];                 // x@Wo^T + bo + bi
// Hidden state double buffer, thread-major scrambled layout:
//   ull element at [u*256 + rt] holds the k-pair h[b][2*k2], h[b][2*k2+1]
//   with rt = (k2>>4)*16 + (b>>1),  u = (b&1)*16 + (k2&15).
//   In the dot, thread tid==rt loads its 32 ulls as [u*256 + tid], u=0..31,
//   which is perfectly coalesced LDG.64. Buffer 0 must be zero at start.
__device__ ull g_hx[2][32 * 256];
__device__ unsigned int g_bar;             // monotonic step barrier counter
__device__ unsigned int g_bar2;            // completion counter (state reset)
__device__ unsigned int g_done[CHUNKS];    // per-chunk gemm completion (-> 12)

// ---------------------------------------------------------------------------
// f32x2 + sync helpers
// ---------------------------------------------------------------------------
__device__ __forceinline__ ull pack2(float x, float y) {
    ull r; asm("mov.b64 %0,{%1,%2};" : "=l"(r) : "f"(x), "f"(y)); return r;
}
__device__ __forceinline__ void unpack2(ull v, float& x, float& y) {
    asm("mov.b64 {%0,%1},%2;" : "=f"(x), "=f"(y) : "l"(v));
}
__device__ __forceinline__ void fma2(ull& c, ull a, ull b) {
    asm("fma.rn.f32x2 %0,%1,%2,%0;" : "+l"(c) : "l"(a), "l"(b));
}
__device__ __forceinline__ void red_add(unsigned int* p, unsigned int v) {
    asm volatile("red.relaxed.gpu.global.add.u32 [%0], %1;" :: "l"(p), "r"(v) : "memory");
}
__device__ __forceinline__ unsigned int ld_acq(const unsigned int* p) {
    unsigned int v;
    asm volatile("ld.acquire.gpu.global.u32 %0, [%1];" : "=r"(v) : "l"(p) : "memory");
    return v;
}
__device__ __forceinline__ void st_rlx(unsigned int* p, unsigned int v) {
    asm volatile("st.relaxed.gpu.global.u32 [%0], %1;" :: "l"(p), "r"(v) : "memory");
}

// ---------------------------------------------------------------------------
// SMEM plan (ull units):
//   rec steady : sW [0,2048) | red [2048,3072) (2048 f) | shn [3072,3200) (256 f)
//   rec epilog : sH 32*257 = 8224 ull  (whole buffer reused)   <- sizing term
//   gemm       : sX/sW 2*128*9 = 2304 ull
// ---------------------------------------------------------------------------
#define MEGA_SMEM (32 * 257 * 8)    // 65792 B
#define KP 9

// ---------------------------------------------------------------------------
// GEMM role: one 128x128 tile of one gate. Publishes g_done[chunk].
// (unchanged from the proven R13 kernel)
// ---------------------------------------------------------------------------
__device__ void gemm_role(
    ull* sm, int local,
    const float* __restrict__ X,
    const float* __restrict__ Wi, const float* __restrict__ Wz,
    const float* __restrict__ Wo,
    const float* __restrict__ bi, const float* __restrict__ bz,
    const float* __restrict__ bo)
{
    const int chunk = local / TILES_PER_CHUNK;
    const int sub   = local % TILES_PER_CHUNK;
    const int z     = sub >> 2;
    const int yt    = sub & 3;

    const float* W  = (z == 0) ? Wi : (z == 1) ? Wz : Wo;
    const float* b1 = (z == 0) ? bi : (z == 1) ? bz : bo;
    float* C = (z == 0) ? g_Ai : (z == 1) ? g_Az : g_Ao;

    ull* sX = sm;
    ull* sW = sm + 128 * KP;

    const int tid  = threadIdx.x;
    const int r    = tid >> 1;
    const int half = tid & 1;
    const size_t xrow = (size_t)(chunk * 128 + r) * 512 + half * 8;
    const size_t wrow = (size_t)(yt * 128 + r) * 512 + half * 8;

    const int m0 = (tid >> 4) * 8;
    const int n0 = (tid & 15) * 8;

    ull acc[8][8];
    #pragma unroll
    for (int i = 0; i < 8; ++i)
        #pragma unroll
        for (int j = 0; j < 8; ++j) acc[i][j] = 0ull;

    float4 px0 = __ldg((const float4*)(X + xrow));
    float4 px1 = __ldg((const float4*)(X + xrow) + 1);
    float4 pw0 = __ldg((const float4*)(W + wrow));
    float4 pw1 = __ldg((const float4*)(W + wrow) + 1);

    for (int kt = 0; kt < 32; ++kt) {
        __syncthreads();
        ull* dx = &sX[r * KP + half * 4];
        dx[0] = pack2(px0.x, px0.y);  dx[1] = pack2(px0.z, px0.w);
        dx[2] = pack2(px1.x, px1.y);  dx[3] = pack2(px1.z, px1.w);
        ull* dw = &sW[r * KP + half * 4];
        dw[0] = pack2(pw0.x, pw0.y);  dw[1] = pack2(pw0.z, pw0.w);
        dw[2] = pack2(pw1.x, pw1.y);  dw[3] = pack2(pw1.z, pw1.w);
        __syncthreads();

        if (kt + 1 < 32) {
            const float4* xp = (const float4*)(X + xrow + (size_t)(kt + 1) * 16);
            const float4* wp = (const float4*)(W + wrow + (size_t)(kt + 1) * 16);
            px0 = __ldg(xp);  px1 = __ldg(xp + 1);
            pw0 = __ldg(wp);  pw1 = __ldg(wp + 1);
        }

        #pragma unroll
        for (int k2 = 0; k2 < 8; ++k2) {
            ull a[8], bb[8];
            #pragma unroll
            for (int i = 0; i < 8; ++i) a[i]  = sX[(m0 + i) * KP + k2];
            #pragma unroll
            for (int j = 0; j < 8; ++j) bb[j] = sW[(n0 + j) * KP + k2];
            #pragma unroll
            for (int i = 0; i < 8; ++i)
                #pragma unroll
                for (int j = 0; j < 8; ++j) fma2(acc[i][j], a[i], bb[j]);
        }
    }

    float bias[8];
    #pragma unroll
    for (int j = 0; j < 8; ++j) {
        int n = yt * 128 + n0 + j;
        bias[j] = __ldg(b1 + n) + __ldg(bi + n);
    }
    #pragma unroll
    for (int i = 0; i < 8; ++i) {
        size_t row = (size_t)(chunk * 128 + m0 + i);
        float v[8];
        #pragma unroll
        for (int j = 0; j < 8; ++j) {
            float lo, hi; unpack2(acc[i][j], lo, hi);
            v[j] = lo + hi + bias[j];
        }
        float4* dst = (float4*)(C + row * 512 + yt * 128 + n0);
        dst[0] = make_float4(v[0], v[1], v[2], v[3]);
        dst[1] = make_float4(v[4], v[5], v[6], v[7]);
    }

    __threadfence();
    __syncthreads();
    if (tid == 0) red_add(&g_done[chunk], 1u);
}

// ---------------------------------------------------------------------------
// Recurrence role (blocks 0..63)
// ---------------------------------------------------------------------------
__device__ void rec_role(
    ull* sm,
    const float* __restrict__ Wi,
    const float* __restrict__ Wy,
    const float* __restrict__ by,
    float* __restrict__ out)
{
    ull*   sW   = sm;                        // Wi slice [j][k2], 8 x 256 ull
    float* red  = (float*)(sm + 2048);       // partials [warp][b*8+j]
    ull*   redu = (ull*)red;
    float* shn  = (float*)(sm + 3072);       // h_new bounce, 256 f

    const int tid  = threadIdx.x;
    const int bid  = blockIdx.x;
    const int j0   = bid * 8;
    const int lane = tid & 31;
    const int w    = tid >> 5;
    const int k2base = (tid >> 4) * 16;      // this thread's 16-k2 slice
    const int gb   = tid >> 3;               // gate-phase batch row
    const int gj   = tid & 7;                // gate-phase column (local j)

    // h_new writer constants (tid < 64): 8 segments of 128B
    const int seg = tid >> 3;                // gp*4 + p
    const int q4  = tid & 7;
    const int w_u = (seg >> 2) * 16 + (bid & 3) * 4 + (seg & 3);
    const int w_dst4 = w_u * 128 + (bid >> 2) * 8 + q4;   // float4 index
    const int w_src  = (seg >> 2) * 128 + (seg & 3) * 32 + q4 * 4;

    // Stage this CTA's 8 Wi rows once (2048 ull)
    const ull* Wi8 = (const ull*)Wi;
    #pragma unroll
    for (int c = 0; c < 8; ++c) {
        int li = c * 256 + tid;
        sW[li] = __ldg(Wi8 + (size_t)(j0 + (li >> 8)) * 256 + (li & 255));
    }
    __syncthreads();

    for (int t = 0; t < T_STEPS; ++t) {
        // Wait for this timestep's pre-activations (every 4 steps)
        if ((t & 3) == 0) {
            if (tid == 0) {
                const unsigned int* f = &g_done[t >> 2];
                while (ld_acq(f) < TILES_PER_CHUNK) { }
            }
            __syncthreads();
        }

        // Gate pre-activations (independent of h; hidden behind the dot)
        size_t ar = ((size_t)(t * 32 + gb)) * 512 + j0 + gj;
        float ai = __ldcg(&g_Ai[ar]);
        float az = __ldcg(&g_Az[ar]);
        float ao = __ldcg(&g_Ao[ar]);

        // h: 32 coalesced LDG.64 straight into registers (no SMEM staging)
        const ull* hb = g_hx[t & 1];
        ull hu[32];
        #pragma unroll
        for (int u = 0; u < 32; ++u) hu[u] = __ldcg(hb + u * 256 + tid);

        // dot: thread covers 2 b x 8 j over its 16 k-pairs; W via broadcast LDS.128
        ull acc[2][8];
        #pragma unroll
        for (int jj = 0; jj < 8; ++jj) { acc[0][jj] = 0ull; acc[1][jj] = 0ull; }
        #pragma unroll
        for (int q2 = 0; q2 < 8; ++q2) {
            #pragma unroll
            for (int jj = 0; jj < 8; ++jj) {
                ulonglong2 wv = *(const ulonglong2*)(sW + jj * 256 + k2base + 2 * q2);
                fma2(acc[0][jj], hu[2 * q2],      wv.x);
                fma2(acc[0][jj], hu[2 * q2 + 1],  wv.y);
                fma2(acc[1][jj], hu[16 + 2 * q2], wv.x);
                fma2(acc[1][jj], hu[17 + 2 * q2], wv.y);
            }
        }

        // collapse k-pair halves + merge the warp's two k2-groups (bfly 16)
        float val[2][8];
        #pragma unroll
        for (int rr = 0; rr < 2; ++rr)
            #pragma unroll
            for (int jj = 0; jj < 8; ++jj) {
                float lo, hi; unpack2(acc[rr][jj], lo, hi);
                float v = lo + hi;
                v += __shfl_xor_sync(0xffffffffu, v, 16);
                val[rr][jj] = v;
            }

        // lanes 0-15 publish warp partials: red[w][b*8+j]
        if (lane < 16) {
            #pragma unroll
            for (int rr = 0; rr < 2; ++rr)
                #pragma unroll
                for (int m = 0; m < 4; ++m)
                    redu[w * 128 + (2 * lane + rr) * 4 + m] =
                        pack2(val[rr][2 * m], val[rr][2 * m + 1]);
        }
        __syncthreads();

        // cross-warp reduce -> hWi[b][j]
        float s = 0.0f;
        #pragma unroll
        for (int ww = 0; ww < 8; ++ww) s += red[ww * 256 + tid];

        // gates (biases pre-folded into A arrays)
        float zi = 1.0f / (1.0f + __expf(-(ai + s)));
        float zz = 1.0f / (1.0f + __expf(-(az + s)));
        float zo = 1.0f / (1.0f + __expf(-(ao + s)));
        float hn = zo * tanhf(zi * zz);

        // bounce h_new through SMEM, then 64 threads do coalesced STG.128
        shn[(gb & 1) * 128 + (gj >> 1) * 32 + (gb >> 1) * 2 + (gj & 1)] = hn;
        __syncthreads();
        if (tid < 64) {
            float4 v4 = *(const float4*)(shn + w_src);
            ((float4*)g_hx[(t + 1) & 1])[w_dst4] = v4;
        }

        // canonical grid barrier: sync, one thread fence+arrive+poll, sync
        __syncthreads();
        if (tid == 0) {
            __threadfence();
            red_add(&g_bar, 1u);
            const unsigned int tgt = (unsigned int)(t + 1) * NREC;
            while (ld_acq(&g_bar) < tgt) { }
        }
        __syncthreads();
    }

    // ---- Epilogue: final h is in buffer 0 ----
    {
        const ull* hb = g_hx[0];
        ull hu[32];
        #pragma unroll
        for (int u = 0; u < 32; ++u) hu[u] = __ldcg(hb + u * 256 + tid);

        __syncthreads();                      // sW/red dead; reuse whole SMEM
        ull* sH = sm;                         // [b][k2], stride 257
        const int bp = tid & 15;
        #pragma unroll
        for (int u = 0; u < 32; ++u) {
            int b  = 2 * bp + (u >> 4);
            int k2 = k2base + (u & 15);
            sH[b * 257 + k2] = hu[u];
        }
        __syncthreads();

        // barrier: everyone has read buffer 0 before anyone zeroes it
        if (tid == 0) {
            red_add(&g_bar, 1u);
            while (ld_acq(&g_bar) < (unsigned int)(T_STEPS + 1) * NREC) { }
        }
        __syncthreads();

        // zero my slice of buffer 0 for the next graph replay
        if (tid < 128) g_hx[0][bid * 128 + tid] = 0ull;

        // out[b][j0+gj] = h[b][:] . Wy[j0+gj][:] + by
        const ull* wy2 = (const ull*)(Wy + (size_t)(j0 + gj) * 512);
        ull o = 0ull;
        #pragma unroll 8
        for (int k2 = 0; k2 < 256; ++k2)
            fma2(o, sH[gb * 257 + k2], __ldg(wy2 + k2));
        float lo, hi; unpack2(o, lo, hi);
        out[gb * 512 + j0 + gj] = lo + hi + __ldg(by + j0 + gj);
    }

    // ---- completion + state reset for the next replay ----
    __threadfence();
    __syncthreads();
    if (tid == 0) red_add(&g_bar2, 1u);
    if (bid == 0) {
        if (tid == 0) { while (ld_acq(&g_bar2) < NREC) { } }
        __syncthreads();
        if (tid == 0) st_rlx(&g_bar, 0u);
        for (int i = tid; i < CHUNKS; i += 256) st_rlx(&g_done[i], 0u);
        __threadfence();
        __syncthreads();
        if (tid == 0) st_rlx(&g_bar2, 0u);
    }
}

// ---------------------------------------------------------------------------
// Fused persistent kernel (1 CTA/SM -> rec CTAs own their SMs)
// ---------------------------------------------------------------------------
__global__ __launch_bounds__(256, 1) void mega_kernel(
    const float* __restrict__ word,
    const float* __restrict__ Wi, const float* __restrict__ bi,
    const float* __restrict__ Wz, const float* __restrict__ bz,
    const float* __restrict__ Wo, const float* __restrict__ bo,
    const float* __restrict__ Wy, const float* __restrict__ by,
    float* __restrict__ out)
{
    extern __shared__ ull sm[];
    if (blockIdx.x < NREC) {
        rec_role(sm, Wi, Wy, by, out);
    } else {
        gemm_role(sm, blockIdx.x - NREC, word, Wi, Wz, Wo, bi, bz, bo);
    }
}

// ---------------------------------------------------------------------------
// Launch (single graph node)
// ---------------------------------------------------------------------------
extern "C" void kernel_launch(void* const* d_in, const int* in_sizes, int n_in,
                              void* d_out, int out_size)
{
    const float* word = (const float*)d_in[0];
    // d_in[1]=Wf, d_in[2]=bf are dead in the reference
    const float* Wi = (const float*)d_in[3];
    const float* bi = (const float*)d_in[4];
    const float* Wz = (const float*)d_in[5];
    const float* bz = (const float*)d_in[6];
    const float* Wo = (const float*)d_in[7];
    const float* bo = (const float*)d_in[8];
    const float* Wy = (const float*)d_in[9];
    const float* by = (const float*)d_in[10];
    float* out = (float*)d_out;

    cudaFuncSetAttribute(mega_kernel,
                         cudaFuncAttributeMaxDynamicSharedMemorySize, MEGA_SMEM);

    mega_kernel<<<NREC + GEMM_CTAS, 256, MEGA_SMEM>>>(
        word, Wi, bi, Wz, bz, Wo, bo, Wy, by, out);
}

// round 16
// speedup vs baseline: 2.9407x; 1.0013x over previous
#include <cuda_runtime.h>
#include <math.h>

typedef unsigned long long ull;

#define T_STEPS 2048
#define BATCH   32
#define DIM     512
#define NA      33554432u     // 2048*32*512

#define NREC      64
#define GEMM_CTAS 6144        // 512 row-chunks * 4 n-tiles * 3 gates
#define CHUNKS    512
#define TILES_PER_CHUNK 12

// ---------------------------------------------------------------------------
// Static device scratch (no allocations anywhere)
// ---------------------------------------------------------------------------
__device__ float g_Ai[NA];                 // x@Wi^T + 2bi          [t*32+b][j]
__device__ float g_Az[NA];                 // x@Wz^T + bz + bi
__device__ float g_Ao[NA];                 // x@Wo^T + bo + bi
// Hidden state double buffer, thread-major scrambled layout:
//   ull element at [u*256 + rt] holds the k-pair h[b][2*k2], h[b][2*k2+1]
//   with rt = (k2>>4)*16 + (b>>1),  u = (b&1)*16 + (k2&15).
//   Thread tid==rt loads its 32 ulls as [u*256 + tid] -> coalesced LDG.64.
//   Buffer 0 must be zero at kernel start (static zero-init + self-reset).
__device__ ull g_hx[2][32 * 256];
__device__ unsigned int g_bar;             // monotonic step barrier counter
__device__ unsigned int g_bar2;            // completion counter (state reset)
__device__ unsigned int g_done[CHUNKS];    // per-chunk gemm completion (-> 12)

// ---------------------------------------------------------------------------
// f32x2 + sync helpers
// ---------------------------------------------------------------------------
__device__ __forceinline__ ull pack2(float x, float y) {
    ull r; asm("mov.b64 %0,{%1,%2};" : "=l"(r) : "f"(x), "f"(y)); return r;
}
__device__ __forceinline__ void unpack2(ull v, float& x, float& y) {
    asm("mov.b64 {%0,%1},%2;" : "=f"(x), "=f"(y) : "l"(v));
}
__device__ __forceinline__ void fma2(ull& c, ull a, ull b) {
    asm("fma.rn.f32x2 %0,%1,%2,%0;" : "+l"(c) : "l"(a), "l"(b));
}
__device__ __forceinline__ void red_add(unsigned int* p, unsigned int v) {
    asm volatile("red.relaxed.gpu.global.add.u32 [%0], %1;" :: "l"(p), "r"(v) : "memory");
}
__device__ __forceinline__ unsigned int ld_acq(const unsigned int* p) {
    unsigned int v;
    asm volatile("ld.acquire.gpu.global.u32 %0, [%1];" : "=r"(v) : "l"(p) : "memory");
    return v;
}
__device__ __forceinline__ void st_rlx(unsigned int* p, unsigned int v) {
    asm volatile("st.relaxed.gpu.global.u32 [%0], %1;" :: "l"(p), "r"(v) : "memory");
}

// sW bank swizzle: odd 16-ull blocks shifted by 4 ull (32B) so the two
// half-warps' broadcast LDS.128 quads land on disjoint banks.
__device__ __forceinline__ int swz(int k2) {
    return k2 ^ (((k2 >> 4) & 1) << 2);
}

// ---------------------------------------------------------------------------
// SMEM plan (ull units):
//   rec steady : sW [0,2048) | red [2048,2368) = 2560 floats (8 warps x 320)
//   rec epilog : sH 32*257 = 8224 ull (whole buffer reused)  <- sizing term
//   gemm       : sX/sW 2*128*9 = 2304 ull
// ---------------------------------------------------------------------------
#define MEGA_SMEM (32 * 257 * 8)    // 65792 B
#define KP 9

// ---------------------------------------------------------------------------
// GEMM role: one 128x128 tile of one gate. Publishes g_done[chunk].
// (unchanged from the proven R13/R15 kernel)
// ---------------------------------------------------------------------------
__device__ void gemm_role(
    ull* sm, int local,
    const float* __restrict__ X,
    const float* __restrict__ Wi, const float* __restrict__ Wz,
    const float* __restrict__ Wo,
    const float* __restrict__ bi, const float* __restrict__ bz,
    const float* __restrict__ bo)
{
    const int chunk = local / TILES_PER_CHUNK;
    const int sub   = local % TILES_PER_CHUNK;
    const int z     = sub >> 2;
    const int yt    = sub & 3;

    const float* W  = (z == 0) ? Wi : (z == 1) ? Wz : Wo;
    const float* b1 = (z == 0) ? bi : (z == 1) ? bz : bo;
    float* C = (z == 0) ? g_Ai : (z == 1) ? g_Az : g_Ao;

    ull* sX = sm;
    ull* sW = sm + 128 * KP;

    const int tid  = threadIdx.x;
    const int r    = tid >> 1;
    const int half = tid & 1;
    const size_t xrow = (size_t)(chunk * 128 + r) * 512 + half * 8;
    const size_t wrow = (size_t)(yt * 128 + r) * 512 + half * 8;

    const int m0 = (tid >> 4) * 8;
    const int n0 = (tid & 15) * 8;

    ull acc[8][8];
    #pragma unroll
    for (int i = 0; i < 8; ++i)
        #pragma unroll
        for (int j = 0; j < 8; ++j) acc[i][j] = 0ull;

    float4 px0 = __ldg((const float4*)(X + xrow));
    float4 px1 = __ldg((const float4*)(X + xrow) + 1);
    float4 pw0 = __ldg((const float4*)(W + wrow));
    float4 pw1 = __ldg((const float4*)(W + wrow) + 1);

    for (int kt = 0; kt < 32; ++kt) {
        __syncthreads();
        ull* dx = &sX[r * KP + half * 4];
        dx[0] = pack2(px0.x, px0.y);  dx[1] = pack2(px0.z, px0.w);
        dx[2] = pack2(px1.x, px1.y);  dx[3] = pack2(px1.z, px1.w);
        ull* dw = &sW[r * KP + half * 4];
        dw[0] = pack2(pw0.x, pw0.y);  dw[1] = pack2(pw0.z, pw0.w);
        dw[2] = pack2(pw1.x, pw1.y);  dw[3] = pack2(pw1.z, pw1.w);
        __syncthreads();

        if (kt + 1 < 32) {
            const float4* xp = (const float4*)(X + xrow + (size_t)(kt + 1) * 16);
            const float4* wp = (const float4*)(W + wrow + (size_t)(kt + 1) * 16);
            px0 = __ldg(xp);  px1 = __ldg(xp + 1);
            pw0 = __ldg(wp);  pw1 = __ldg(wp + 1);
        }

        #pragma unroll
        for (int k2 = 0; k2 < 8; ++k2) {
            ull a[8], bb[8];
            #pragma unroll
            for (int i = 0; i < 8; ++i) a[i]  = sX[(m0 + i) * KP + k2];
            #pragma unroll
            for (int j = 0; j < 8; ++j) bb[j] = sW[(n0 + j) * KP + k2];
            #pragma unroll
            for (int i = 0; i < 8; ++i)
                #pragma unroll
                for (int j = 0; j < 8; ++j) fma2(acc[i][j], a[i], bb[j]);
        }
    }

    float bias[8];
    #pragma unroll
    for (int j = 0; j < 8; ++j) {
        int n = yt * 128 + n0 + j;
        bias[j] = __ldg(b1 + n) + __ldg(bi + n);
    }
    #pragma unroll
    for (int i = 0; i < 8; ++i) {
        size_t row = (size_t)(chunk * 128 + m0 + i);
        float v[8];
        #pragma unroll
        for (int j = 0; j < 8; ++j) {
            float lo, hi; unpack2(acc[i][j], lo, hi);
            v[j] = lo + hi + bias[j];
        }
        float4* dst = (float4*)(C + row * 512 + yt * 128 + n0);
        dst[0] = make_float4(v[0], v[1], v[2], v[3]);
        dst[1] = make_float4(v[4], v[5], v[6], v[7]);
    }

    __threadfence();
    __syncthreads();
    if (tid == 0) red_add(&g_done[chunk], 1u);
}

// ---------------------------------------------------------------------------
// Recurrence role (blocks 0..63)
// ---------------------------------------------------------------------------
__device__ void rec_role(
    ull* sm,
    const float* __restrict__ Wi,
    const float* __restrict__ Wy,
    const float* __restrict__ by,
    float* __restrict__ out)
{
    ull*   sW  = sm;                       // Wi slice [j][swz(k2)], 8 x 256 ull
    float* red = (float*)(sm + 2048);      // partials: 8 warps x (16 lanes x 20f)

    const int tid  = threadIdx.x;
    const int bid  = blockIdx.x;
    const int j0   = bid * 8;
    const int lane = tid & 31;
    const int w    = tid >> 5;
    const int k2base = (tid >> 4) * 16;    // this thread's 16-k2 slice
    const int kswz   = ((k2base >> 4) & 1) << 2;   // sW swizzle for this slice
    const int gb   = tid >> 3;             // gate-phase batch row
    const int gj   = tid & 7;              // gate-phase column (local j)

    // reduction read offset: value (b,j) lives at red[ww*320 + (b>>1)*20 + (b&1)*8 + j]
    const int roff = (gb >> 1) * 20 + (gb & 1) * 8 + gj;

    // h_new direct-store offset (scrambled layout)
    const int kcol = j0 + gj;
    const int k2w  = kcol >> 1;
    const int hoff = (((gb & 1) * 16 + (k2w & 15)) * 256 +
                      ((k2w >> 4) * 16 + (gb >> 1))) * 2 + (kcol & 1);

    // Stage this CTA's 8 Wi rows once (2048 ull), applying the bank swizzle
    const ull* Wi8 = (const ull*)Wi;
    #pragma unroll
    for (int c = 0; c < 8; ++c) {
        int li = c * 256 + tid;
        int jl = li >> 8, kk = li & 255;
        sW[jl * 256 + swz(kk)] = __ldg(Wi8 + (size_t)(j0 + jl) * 256 + kk);
    }
    __syncthreads();

    for (int t = 0; t < T_STEPS; ++t) {
        // Wait for this timestep's pre-activations (every 4 steps)
        if ((t & 3) == 0) {
            if (tid == 0) {
                const unsigned int* f = &g_done[t >> 2];
                while (ld_acq(f) < TILES_PER_CHUNK) { }
            }
            __syncthreads();
        }

        const ull* hb = g_hx[t & 1];

        // --- software-pipelined h-load + dot ---
        // batch g uses h ulls {4g..4g+3} (b0) and {16+4g..16+4g+3} (b1)
        ull ha[8], hn2[8];
        #pragma unroll
        for (int i = 0; i < 4; ++i) {
            ha[i]     = __ldcg(hb + (i)      * 256 + tid);
            ha[4 + i] = __ldcg(hb + (16 + i) * 256 + tid);
        }

        // gate pre-activations (off critical path; consumed after the dot)
        size_t ar = ((size_t)(t * 32 + gb)) * 512 + j0 + gj;
        float ai = __ldcg(&g_Ai[ar]);
        float az = __ldcg(&g_Az[ar]);
        float ao = __ldcg(&g_Ao[ar]);

        ull acc[2][8];
        #pragma unroll
        for (int jj = 0; jj < 8; ++jj) { acc[0][jj] = 0ull; acc[1][jj] = 0ull; }

        #pragma unroll
        for (int g = 0; g < 4; ++g) {
            if (g < 3) {
                #pragma unroll
                for (int i = 0; i < 4; ++i) {
                    hn2[i]     = __ldcg(hb + (4 * (g + 1) + i)      * 256 + tid);
                    hn2[4 + i] = __ldcg(hb + (16 + 4 * (g + 1) + i) * 256 + tid);
                }
            }
            #pragma unroll
            for (int q = 0; q < 2; ++q) {
                int k2 = k2base + ((2 * (2 * g + q)) ^ kswz);
                #pragma unroll
                for (int jj = 0; jj < 8; ++jj) {
                    ulonglong2 wv = *(const ulonglong2*)(sW + jj * 256 + k2);
                    fma2(acc[0][jj], ha[2 * q],     wv.x);
                    fma2(acc[0][jj], ha[2 * q + 1], wv.y);
                    fma2(acc[1][jj], ha[4 + 2 * q],     wv.x);
                    fma2(acc[1][jj], ha[5 + 2 * q],     wv.y);
                }
            }
            #pragma unroll
            for (int i = 0; i < 8; ++i) ha[i] = hn2[i];
        }

        // collapse k-pair halves + merge the warp's two k2-groups (bfly 16)
        float val[2][8];
        #pragma unroll
        for (int rr = 0; rr < 2; ++rr)
            #pragma unroll
            for (int jj = 0; jj < 8; ++jj) {
                float lo, hi; unpack2(acc[rr][jj], lo, hi);
                float v = lo + hi;
                v += __shfl_xor_sync(0xffffffffu, v, 16);
                val[rr][jj] = v;
            }

        // lanes 0-15 publish: pitch-20 layout, 4x STS.128, ~2 wf each
        if (lane < 16) {
            float* dst = red + w * 320 + lane * 20;
            *(float4*)(dst)      = make_float4(val[0][0], val[0][1], val[0][2], val[0][3]);
            *(float4*)(dst + 4)  = make_float4(val[0][4], val[0][5], val[0][6], val[0][7]);
            *(float4*)(dst + 8)  = make_float4(val[1][0], val[1][1], val[1][2], val[1][3]);
            *(float4*)(dst + 12) = make_float4(val[1][4], val[1][5], val[1][6], val[1][7]);
        }
        __syncthreads();

        // cross-warp reduce -> hWi[b][j]
        float s = 0.0f;
        #pragma unroll
        for (int ww = 0; ww < 8; ++ww) s += red[ww * 320 + roff];

        // gates (biases pre-folded into A arrays)
        float zi = 1.0f / (1.0f + __expf(-(ai + s)));
        float zz = 1.0f / (1.0f + __expf(-(az + s)));
        float zo = 1.0f / (1.0f + __expf(-(ao + s)));
        float hn = zo * tanhf(zi * zz);

        // direct store into scrambled layout (8 x 16B sectors per warp)
        ((float*)g_hx[(t + 1) & 1])[hoff] = hn;

        // grid barrier: sync, tid0 fence+arrive+poll, sync
        __syncthreads();
        if (tid == 0) {
            __threadfence();
            red_add(&g_bar, 1u);
            const unsigned int tgt = (unsigned int)(t + 1) * NREC;
            while (ld_acq(&g_bar) < tgt) { }
        }
        __syncthreads();
    }

    // ---- Epilogue: final h is in buffer 0 ----
    {
        const ull* hb = g_hx[0];
        ull hu[32];
        #pragma unroll
        for (int u = 0; u < 32; ++u) hu[u] = __ldcg(hb + u * 256 + tid);

        __syncthreads();                      // sW/red dead; reuse whole SMEM
        ull* sH = sm;                         // [b][k2], stride 257
        const int bp = tid & 15;
        #pragma unroll
        for (int u = 0; u < 32; ++u) {
            int b  = 2 * bp + (u >> 4);
            int k2 = k2base + (u & 15);
            sH[b * 257 + k2] = hu[u];
        }
        __syncthreads();

        // barrier: everyone has read buffer 0 before anyone zeroes it
        if (tid == 0) {
            red_add(&g_bar, 1u);
            while (ld_acq(&g_bar) < (unsigned int)(T_STEPS + 1) * NREC) { }
        }
        __syncthreads();

        // zero my slice of buffer 0 for the next graph replay
        if (tid < 128) g_hx[0][bid * 128 + tid] = 0ull;

        // out[b][j0+gj] = h[b][:] . Wy[j0+gj][:] + by
        const ull* wy2 = (const ull*)(Wy + (size_t)(j0 + gj) * 512);
        ull o = 0ull;
        #pragma unroll 8
        for (int k2 = 0; k2 < 256; ++k2)
            fma2(o, sH[gb * 257 + k2], __ldg(wy2 + k2));
        float lo, hi; unpack2(o, lo, hi);
        out[gb * 512 + j0 + gj] = lo + hi + __ldg(by + j0 + gj);
    }

    // ---- completion + state reset for the next replay ----
    __threadfence();
    __syncthreads();
    if (tid == 0) red_add(&g_bar2, 1u);
    if (bid == 0) {
        if (tid == 0) { while (ld_acq(&g_bar2) < NREC) { } }
        __syncthreads();
        if (tid == 0) st_rlx(&g_bar, 0u);
        for (int i = tid; i < CHUNKS; i += 256) st_rlx(&g_done[i], 0u);
        __threadfence();
        __syncthreads();
        if (tid == 0) st_rlx(&g_bar2, 0u);
    }
}

// ---------------------------------------------------------------------------
// Fused persistent kernel (1 CTA/SM -> rec CTAs own their SMs)
// ---------------------------------------------------------------------------
__global__ __launch_bounds__(256, 1) void mega_kernel(
    const float* __restrict__ word,
    const float* __restrict__ Wi, const float* __restrict__ bi,
    const float* __restrict__ Wz, const float* __restrict__ bz,
    const float* __restrict__ Wo, const float* __restrict__ bo,
    const float* __restrict__ Wy, const float* __restrict__ by,
    float* __restrict__ out)
{
    extern __shared__ ull sm[];
    if (blockIdx.x < NREC) {
        rec_role(sm, Wi, Wy, by, out);
    } else {
        gemm_role(sm, blockIdx.x - NREC, word, Wi, Wz, Wo, bi, bz, bo);
    }
}

// ---------------------------------------------------------------------------
// Launch (single graph node)
// ---------------------------------------------------------------------------
extern "C" void kernel_launch(void* const* d_in, const int* in_sizes, int n_in,
                              void* d_out, int out_size)
{
    const float* word = (const float*)d_in[0];
    // d_in[1]=Wf, d_in[2]=bf are dead in the reference
    const float* Wi = (const float*)d_in[3];
    const float* bi = (const float*)d_in[4];
    const float* Wz = (const float*)d_in[5];
    const float* bz = (const float*)d_in[6];
    const float* Wo = (const float*)d_in[7];
    const float* bo = (const float*)d_in[8];
    const float* Wy = (const float*)d_in[9];
    const float* by = (const float*)d_in[10];
    float* out = (float*)d_out;

    cudaFuncSetAttribute(mega_kernel,
                         cudaFuncAttributeMaxDynamicSharedMemorySize, MEGA_SMEM);

    mega_kernel<<<NREC + GEMM_CTAS, 256, MEGA_SMEM>>>(
        word, Wi, bi, Wz, bz, Wo, bo, Wy, by, out);
}